// round 1
// baseline (speedup 1.0000x reference)
#include <cuda_runtime.h>
#include <cstdint>
#include <cstddef>

// RNN_49297634623576: out = fc_w @ tanh(w_ih @ x[:,27,:] + b_ih + b_hh) + fc_b
// hx == 0  =>  w_hh is unused.
//
// Strategy: issue-bound fp32 kernel using Blackwell packed fma.rn.f32x2 (FFMA2).
//  - Layer 1 (64x28): K-packed. Weight pairs {w[j][2p], w[j][2p+1]} live in shared
//    as 8-byte words -> one warp-uniform LDS.64 feeds 4 FFMA2 (4 batch rows/thread).
//  - Layer 2 (10x64): row-packed. fc weights pre-duplicated {w,w} in shared; h values
//    of row-pairs packed into f32x2, accumulated into f32x2 per output.
//  - tanh(x) = 1 - 2/(exp(2x)+1) via __expf (accurate to ~1e-6, well under 1e-3 gate).

#define NB   65536
#define NIN  28
#define NHID 64
#define NOUT 10
#define RPT  4      // batch rows per thread
#define TPB  128    // threads per block -> 512 rows/block -> 128 blocks

typedef unsigned long long u64;

__device__ __forceinline__ u64 pk2(float a, float b) {
    u64 r; asm("mov.b64 %0,{%1,%2};" : "=l"(r) : "f"(a), "f"(b)); return r;
}
__device__ __forceinline__ void upk2(u64 v, float& a, float& b) {
    asm("mov.b64 {%0,%1},%2;" : "=f"(a), "=f"(b) : "l"(v));
}
__device__ __forceinline__ u64 ffma2(u64 a, u64 b, u64 c) {
    u64 d; asm("fma.rn.f32x2 %0,%1,%2,%3;" : "=l"(d) : "l"(a), "l"(b), "l"(c)); return d;
}
__device__ __forceinline__ float hsum2(u64 v) {
    float a, b; upk2(v, a, b); return a + b;
}
__device__ __forceinline__ float tanh_fast(float x) {
    // 1 - 2/(e^{2x}+1); exact limits at +/-inf, ~1e-6 rel accuracy.
    float e = __expf(2.0f * x);
    return 1.0f - __fdividef(2.0f, e + 1.0f);
}

__global__ void __launch_bounds__(TPB, 1)
rnn_fused_kernel(const float* __restrict__ x,
                 const float* __restrict__ w_ih,
                 const float* __restrict__ b_ih,
                 const float* __restrict__ b_hh,
                 const float* __restrict__ fc_w,
                 const float* __restrict__ fc_b,
                 float* __restrict__ out)
{
    __shared__ u64   s_w[NHID][NIN / 2];   // {w[j][2p], w[j][2p+1]}
    __shared__ float s_b[NHID];            // b_ih + b_hh
    __shared__ u64   s_fc[NOUT][NHID];     // {fc_w[k][j], fc_w[k][j]} duplicated
    __shared__ float s_fcb[NOUT];

    const int tid = threadIdx.x;

    for (int i = tid; i < NHID * (NIN / 2); i += TPB) {
        int j = i / (NIN / 2), p = i % (NIN / 2);
        s_w[j][p] = pk2(w_ih[j * NIN + 2 * p], w_ih[j * NIN + 2 * p + 1]);
    }
    for (int i = tid; i < NHID; i += TPB) s_b[i] = b_ih[i] + b_hh[i];
    for (int i = tid; i < NOUT * NHID; i += TPB) {
        float w = fc_w[i];
        s_fc[i / NHID][i % NHID] = pk2(w, w);
    }
    if (tid < NOUT) s_fcb[tid] = fc_b[tid];
    __syncthreads();

    const long long base = ((long long)blockIdx.x * TPB + tid) * RPT;

    // Load last input row (28 floats) for RPT batch rows. Offset 756 is 16B aligned.
    u64 in[RPT][NIN / 2];
#pragma unroll
    for (int r = 0; r < RPT; r++) {
        const float4* p = reinterpret_cast<const float4*>(x + (size_t)(base + r) * 784 + 756);
#pragma unroll
        for (int q = 0; q < 7; q++) {
            float4 v = p[q];
            in[r][2 * q]     = pk2(v.x, v.y);
            in[r][2 * q + 1] = pk2(v.z, v.w);
        }
    }

    // FC accumulators: oa[0][k] = {row0, row1}, oa[1][k] = {row2, row3}
    u64 oa[2][NOUT];
#pragma unroll
    for (int k = 0; k < NOUT; k++) { oa[0][k] = 0ull; oa[1][k] = 0ull; }

#pragma unroll 2
    for (int j = 0; j < NHID; j++) {
        u64 a0 = 0ull, a1 = 0ull, a2 = 0ull, a3 = 0ull;
#pragma unroll
        for (int p = 0; p < NIN / 2; p++) {
            u64 w = s_w[j][p];               // warp-uniform LDS.64 broadcast
            a0 = ffma2(w, in[0][p], a0);
            a1 = ffma2(w, in[1][p], a1);
            a2 = ffma2(w, in[2][p], a2);
            a3 = ffma2(w, in[3][p], a3);
        }
        const float bj = s_b[j];
        float h0 = tanh_fast(hsum2(a0) + bj);
        float h1 = tanh_fast(hsum2(a1) + bj);
        float h2 = tanh_fast(hsum2(a2) + bj);
        float h3 = tanh_fast(hsum2(a3) + bj);
        u64 hp01 = pk2(h0, h1);
        u64 hp23 = pk2(h2, h3);
#pragma unroll
        for (int k = 0; k < NOUT; k++) {
            u64 fw = s_fc[k][j];             // {w,w} duplicated
            oa[0][k] = ffma2(fw, hp01, oa[0][k]);
            oa[1][k] = ffma2(fw, hp23, oa[1][k]);
        }
    }

    // Epilogue: add fc_b and store 10 floats per row as 5x STG.64 (rows are 8B aligned).
    float res[RPT][NOUT];
#pragma unroll
    for (int k = 0; k < NOUT; k++) {
        float fb = s_fcb[k];
        float v0, v1, v2, v3;
        upk2(oa[0][k], v0, v1);
        upk2(oa[1][k], v2, v3);
        res[0][k] = v0 + fb; res[1][k] = v1 + fb;
        res[2][k] = v2 + fb; res[3][k] = v3 + fb;
    }
#pragma unroll
    for (int r = 0; r < RPT; r++) {
        float2* o2 = reinterpret_cast<float2*>(out + (size_t)(base + r) * NOUT);
#pragma unroll
        for (int k = 0; k < NOUT / 2; k++) {
            o2[k] = make_float2(res[r][2 * k], res[r][2 * k + 1]);
        }
    }
}

extern "C" void kernel_launch(void* const* d_in, const int* in_sizes, int n_in,
                              void* d_out, int out_size)
{
    (void)in_sizes; (void)n_in; (void)out_size;
    const float* x    = (const float*)d_in[0];
    const float* w_ih = (const float*)d_in[1];
    // d_in[2] = w_hh : unused (hx == 0)
    const float* b_ih = (const float*)d_in[3];
    const float* b_hh = (const float*)d_in[4];
    const float* fc_w = (const float*)d_in[5];
    const float* fc_b = (const float*)d_in[6];
    float* out = (float*)d_out;

    const int rows_per_block = TPB * RPT;          // 512
    const int blocks = NB / rows_per_block;        // 128, exact

    rnn_fused_kernel<<<blocks, TPB>>>(x, w_ih, b_ih, b_hh, fc_w, fc_b, out);
}